// round 5
// baseline (speedup 1.0000x reference)
#include <cuda_runtime.h>
#include <cuda_bf16.h>
#include <math.h>
#include <stdint.h>

// Problem constants
#define BB 4
#define SS 2048
#define DD 1024
#define HH 16
#define DKK 64
#define MM (BB * SS)   // 8192
#define GK 1024

// ---------------- scratch (device globals; no runtime alloc allowed) --------
__device__ float g_qp[(size_t)MM * DD];
__device__ float g_kp[(size_t)MM * DD];
__device__ float g_vp[(size_t)MM * DD];
__device__ float g_ao[(size_t)MM * DD];

// ==================== helpers ================================================
__device__ __forceinline__ uint32_t f2tf32(float x) {
    uint32_t u;
    asm("cvt.rna.tf32.f32 %0, %1;" : "=r"(u) : "f"(x));
    return u;
}

// m16n8k8 tf32 mma (legacy tensor core; valid on compute_103 virtual arch)
__device__ __forceinline__ void mma_tf32(float* c, const uint32_t* a,
                                         const uint32_t* b) {
    asm volatile(
        "mma.sync.aligned.m16n8k8.row.col.f32.tf32.tf32.f32 "
        "{%0,%1,%2,%3}, {%4,%5,%6,%7}, {%8,%9}, {%0,%1,%2,%3};"
        : "+f"(c[0]), "+f"(c[1]), "+f"(c[2]), "+f"(c[3])
        : "r"(a[0]), "r"(a[1]), "r"(a[2]), "r"(a[3]), "r"(b[0]), "r"(b[1]));
}

// ==================== GEMM: C[M,N] = A[M,K] @ W[K,N] + bias ================
// (unchanged — 4 GEMMs total ~520us; flash is the profiled bottleneck)
#define GTM 128
#define GTN 128
#define GKC 32
#define ALD 36
#define BLD 136
#define ABUF (GTM * ALD)
#define BBUF (GKC * BLD)
#define GSM_FLOATS (2 * (ABUF + BBUF))   // 71680 B

__global__ void __launch_bounds__(256)
gemm_mma(const float* __restrict__ A, const float* __restrict__ W,
         const float* __restrict__ bias, float* __restrict__ C) {
    extern __shared__ __align__(16) uint32_t gsm[];

    const int tid = threadIdx.x;
    const int wid = tid >> 5, lane = tid & 31;
    const int gid = lane >> 2, tg = lane & 3;
    const int bm = blockIdx.y * GTM, bn = blockIdx.x * GTN;
    const int wm = (wid >> 1) * 32, wn = (wid & 1) * 64;

    float acc[2][8][4];
#pragma unroll
    for (int mt = 0; mt < 2; mt++)
#pragma unroll
        for (int nt = 0; nt < 8; nt++)
#pragma unroll
            for (int c = 0; c < 4; c++) acc[mt][nt][c] = 0.0f;

    const int arow = tid >> 3, acol = (tid & 7) * 4;
    const int brow = tid >> 5, bcol = (tid & 31) * 4;

    float4 ar[4], br[4];

    auto loadAB = [&](int kc) {
        const float* ap = A + (size_t)(bm + arow) * GK + kc * GKC + acol;
#pragma unroll
        for (int i = 0; i < 4; i++)
            ar[i] = *(const float4*)(ap + (size_t)(32 * i) * GK);
        const float* bp = W + (size_t)(kc * GKC + brow) * DD + bn + bcol;
#pragma unroll
        for (int i = 0; i < 4; i++)
            br[i] = *(const float4*)(bp + (size_t)(8 * i) * DD);
    };

    auto storeAB = [&](int buf) {
        uint32_t* As = gsm + buf * ABUF;
        uint32_t* Bs = gsm + 2 * ABUF + buf * BBUF;
#pragma unroll
        for (int i = 0; i < 4; i++) {
            uint32_t* p = As + (arow + 32 * i) * ALD + acol;
            p[0] = f2tf32(ar[i].x); p[1] = f2tf32(ar[i].y);
            p[2] = f2tf32(ar[i].z); p[3] = f2tf32(ar[i].w);
        }
#pragma unroll
        for (int i = 0; i < 4; i++) {
            uint32_t* p = Bs + (brow + 8 * i) * BLD + bcol;
            p[0] = f2tf32(br[i].x); p[1] = f2tf32(br[i].y);
            p[2] = f2tf32(br[i].z); p[3] = f2tf32(br[i].w);
        }
    };

    auto compute = [&](int buf) {
        const uint32_t* As = gsm + buf * ABUF;
        const uint32_t* Bs = gsm + 2 * ABUF + buf * BBUF;
#pragma unroll
        for (int ks = 0; ks < 4; ks++) {
            const int k0 = ks * 8;
            uint32_t af[2][4], bf[8][2];
#pragma unroll
            for (int mt = 0; mt < 2; mt++) {
                const uint32_t* p = As + (wm + mt * 16 + gid) * ALD + k0 + tg;
                af[mt][0] = p[0];
                af[mt][1] = p[8 * ALD];
                af[mt][2] = p[4];
                af[mt][3] = p[8 * ALD + 4];
            }
#pragma unroll
            for (int nt = 0; nt < 8; nt++) {
                const uint32_t* p = Bs + (k0 + tg) * BLD + wn + nt * 8 + gid;
                bf[nt][0] = p[0];
                bf[nt][1] = p[4 * BLD];
            }
#pragma unroll
            for (int mt = 0; mt < 2; mt++)
#pragma unroll
                for (int nt = 0; nt < 8; nt++)
                    mma_tf32(acc[mt][nt], af[mt], bf[nt]);
        }
    };

    loadAB(0);
    storeAB(0);
    __syncthreads();
    for (int kc = 0; kc < GK / GKC; kc++) {
        const int buf = kc & 1;
        if (kc < GK / GKC - 1) loadAB(kc + 1);
        compute(buf);
        if (kc < GK / GKC - 1) storeAB(buf ^ 1);
        __syncthreads();
    }

#pragma unroll
    for (int mt = 0; mt < 2; mt++) {
        const int row = bm + wm + mt * 16 + gid;
#pragma unroll
        for (int nt = 0; nt < 8; nt++) {
            const int col = bn + wn + nt * 8 + 2 * tg;
            const float b0 = __ldg(bias + col), b1 = __ldg(bias + col + 1);
            float2 v0 = make_float2(acc[mt][nt][0] + b0, acc[mt][nt][1] + b1);
            float2 v1 = make_float2(acc[mt][nt][2] + b0, acc[mt][nt][3] + b1);
            *(float2*)(C + (size_t)row * DD + col) = v0;
            *(float2*)(C + (size_t)(row + 8) * DD + col) = v1;
        }
    }
}

// ==================== Flash attention on mma.sync tf32 ======================
// CTA: one (b, h, 128-q block). 8 warps as 4(M) x 2(N); warp tile 32x32.
// Cross-warp softmax between N-half partners via smem partials.
// exp2 domain: Q pre-scaled by 0.125*log2(e).
#define FBQ 128
#define FQLD 68   // Q/K/P smem stride
#define FVLD 72   // V smem stride
// floats: Qs 8704 + Ks 4352 + Vs 4608 + Ps 8704 + redm 256 + reds 256
#define FSM_FLOATS (FBQ * FQLD + 64 * FQLD + 64 * FVLD + FBQ * FQLD + 512)

__global__ void __launch_bounds__(256, 2)
flash_mma(const float* __restrict__ Qp, const float* __restrict__ Kp,
          const float* __restrict__ Vp, float* __restrict__ Op) {
    extern __shared__ __align__(16) uint32_t fsm[];
    uint32_t* Qs = fsm;                     // [128][68]
    uint32_t* Ks = Qs + FBQ * FQLD;         // [64][68]
    uint32_t* Vs = Ks + 64 * FQLD;          // [64][72]
    uint32_t* Ps = Vs + 64 * FVLD;          // [128][68]
    float* redm = (float*)(Ps + FBQ * FQLD);   // [128][2]
    float* reds = redm + 256;                  // [128][2]

    const int tid = threadIdx.x;
    const int wid = tid >> 5, lane = tid & 31;
    const int gid = lane >> 2, tg = lane & 3;
    const int q0 = blockIdx.x * FBQ;
    const int h = blockIdx.y, b = blockIdx.z;
    const size_t base = (size_t)b * SS * DD + (size_t)h * DKK;
    const int wm = (wid >> 1) * 32;        // M group: 0,32,64,96
    const int wh = wid & 1;                // N half
    const int wn = wh * 32;

    // Load Q tile once, folding in 0.125 * log2(e)
    const float qscale = 0.125f * 1.44269504088896340736f;
    for (int i = tid; i < FBQ * 16; i += 256) {
        const int r = i >> 4, c = (i & 15) * 4;
        float4 v = *(const float4*)(Qp + base + (size_t)(q0 + r) * DD + c);
        uint32_t* p = Qs + r * FQLD + c;
        p[0] = f2tf32(v.x * qscale); p[1] = f2tf32(v.y * qscale);
        p[2] = f2tf32(v.z * qscale); p[3] = f2tf32(v.w * qscale);
    }

    float m_i[2][2], l_i[2][2];
    float oacc[2][4][4];
#pragma unroll
    for (int mt = 0; mt < 2; mt++) {
        m_i[mt][0] = -1e30f; m_i[mt][1] = -1e30f;
        l_i[mt][0] = 0.0f;   l_i[mt][1] = 0.0f;
#pragma unroll
        for (int nt = 0; nt < 4; nt++)
#pragma unroll
            for (int c = 0; c < 4; c++) oacc[mt][nt][c] = 0.0f;
    }

    for (int kb = 0; kb < SS / 64; kb++) {
        __syncthreads();   // prev PV / P reads done before overwrite
        for (int i = tid; i < 64 * 16; i += 256) {
            const int r = i >> 4, c = (i & 15) * 4;
            const size_t g = base + (size_t)(kb * 64 + r) * DD + c;
            float4 kv = *(const float4*)(Kp + g);
            uint32_t* pk = Ks + r * FQLD + c;
            pk[0] = f2tf32(kv.x); pk[1] = f2tf32(kv.y);
            pk[2] = f2tf32(kv.z); pk[3] = f2tf32(kv.w);
            float4 vv = *(const float4*)(Vp + g);
            uint32_t* pv = Vs + r * FVLD + c;
            pv[0] = f2tf32(vv.x); pv[1] = f2tf32(vv.y);
            pv[2] = f2tf32(vv.z); pv[3] = f2tf32(vv.w);
        }
        __syncthreads();

        // S = Q @ K^T for this warp's 32x32 subtile (keys wn..wn+31)
        float s[2][4][4];
#pragma unroll
        for (int mt = 0; mt < 2; mt++)
#pragma unroll
            for (int nt = 0; nt < 4; nt++)
#pragma unroll
                for (int c = 0; c < 4; c++) s[mt][nt][c] = 0.0f;

#pragma unroll
        for (int ks = 0; ks < 8; ks++) {
            const int k0 = ks * 8;
            uint32_t af[2][4], bf[4][2];
#pragma unroll
            for (int mt = 0; mt < 2; mt++) {
                const uint32_t* ap = Qs + (wm + mt * 16 + gid) * FQLD + k0 + tg;
                af[mt][0] = ap[0];
                af[mt][1] = ap[8 * FQLD];
                af[mt][2] = ap[4];
                af[mt][3] = ap[8 * FQLD + 4];
            }
#pragma unroll
            for (int nt = 0; nt < 4; nt++) {
                const uint32_t* bp = Ks + (wn + nt * 8 + gid) * FQLD + k0 + tg;
                bf[nt][0] = bp[0];
                bf[nt][1] = bp[4];
            }
#pragma unroll
            for (int mt = 0; mt < 2; mt++)
#pragma unroll
                for (int nt = 0; nt < 4; nt++)
                    mma_tf32(s[mt][nt], af[mt], bf[nt]);
        }

        // ---- cross-warp online softmax (base 2) ----
        // partial row max over this warp's 32 key-cols
        float mx[2][2];
#pragma unroll
        for (int mt = 0; mt < 2; mt++) {
            float m0 = -1e30f, m1 = -1e30f;
#pragma unroll
            for (int nt = 0; nt < 4; nt++) {
                m0 = fmaxf(m0, fmaxf(s[mt][nt][0], s[mt][nt][1]));
                m1 = fmaxf(m1, fmaxf(s[mt][nt][2], s[mt][nt][3]));
            }
#pragma unroll
            for (int m = 1; m <= 2; m <<= 1) {
                m0 = fmaxf(m0, __shfl_xor_sync(0xffffffffu, m0, m));
                m1 = fmaxf(m1, __shfl_xor_sync(0xffffffffu, m1, m));
            }
            mx[mt][0] = m0; mx[mt][1] = m1;
        }
        if (tg == 0) {
#pragma unroll
            for (int mt = 0; mt < 2; mt++) {
                const int r0 = wm + mt * 16 + gid;
                redm[2 * r0 + wh] = mx[mt][0];
                redm[2 * (r0 + 8) + wh] = mx[mt][1];
            }
        }
        __syncthreads();

        float mnew[2][2], corr[2][2];
#pragma unroll
        for (int mt = 0; mt < 2; mt++) {
            const int r0 = wm + mt * 16 + gid;
            float2 pm0 = *(float2*)&redm[2 * r0];
            float2 pm1 = *(float2*)&redm[2 * (r0 + 8)];
            mnew[mt][0] = fmaxf(m_i[mt][0], fmaxf(pm0.x, pm0.y));
            mnew[mt][1] = fmaxf(m_i[mt][1], fmaxf(pm1.x, pm1.y));
            corr[mt][0] = exp2f(m_i[mt][0] - mnew[mt][0]);
            corr[mt][1] = exp2f(m_i[mt][1] - mnew[mt][1]);
        }

        // exp2 + partial sums
#pragma unroll
        for (int mt = 0; mt < 2; mt++) {
            float s0 = 0.0f, s1 = 0.0f;
#pragma unroll
            for (int nt = 0; nt < 4; nt++) {
                s[mt][nt][0] = exp2f(s[mt][nt][0] - mnew[mt][0]);
                s[mt][nt][1] = exp2f(s[mt][nt][1] - mnew[mt][0]);
                s[mt][nt][2] = exp2f(s[mt][nt][2] - mnew[mt][1]);
                s[mt][nt][3] = exp2f(s[mt][nt][3] - mnew[mt][1]);
                s0 += s[mt][nt][0] + s[mt][nt][1];
                s1 += s[mt][nt][2] + s[mt][nt][3];
            }
#pragma unroll
            for (int m = 1; m <= 2; m <<= 1) {
                s0 += __shfl_xor_sync(0xffffffffu, s0, m);
                s1 += __shfl_xor_sync(0xffffffffu, s1, m);
            }
            mx[mt][0] = s0; mx[mt][1] = s1;   // reuse mx as sum holder
        }
        if (tg == 0) {
#pragma unroll
            for (int mt = 0; mt < 2; mt++) {
                const int r0 = wm + mt * 16 + gid;
                reds[2 * r0 + wh] = mx[mt][0];
                reds[2 * (r0 + 8) + wh] = mx[mt][1];
            }
        }

        // write P fragments (C layout) to smem as tf32 (this warp's 32 cols)
#pragma unroll
        for (int mt = 0; mt < 2; mt++)
#pragma unroll
            for (int nt = 0; nt < 4; nt++) {
                uint32_t* pp = Ps + (wm + mt * 16 + gid) * FQLD
                             + wn + nt * 8 + 2 * tg;
                uint2 lo = make_uint2(f2tf32(s[mt][nt][0]), f2tf32(s[mt][nt][1]));
                uint2 hi = make_uint2(f2tf32(s[mt][nt][2]), f2tf32(s[mt][nt][3]));
                *(uint2*)pp = lo;
                *(uint2*)(pp + 8 * FQLD) = hi;
            }
        __syncthreads();

        // combine sums, rescale O
#pragma unroll
        for (int mt = 0; mt < 2; mt++) {
            const int r0 = wm + mt * 16 + gid;
            float2 ps0 = *(float2*)&reds[2 * r0];
            float2 ps1 = *(float2*)&reds[2 * (r0 + 8)];
            l_i[mt][0] = l_i[mt][0] * corr[mt][0] + ps0.x + ps0.y;
            l_i[mt][1] = l_i[mt][1] * corr[mt][1] + ps1.x + ps1.y;
            m_i[mt][0] = mnew[mt][0];
            m_i[mt][1] = mnew[mt][1];
#pragma unroll
            for (int nt = 0; nt < 4; nt++) {
                oacc[mt][nt][0] *= corr[mt][0]; oacc[mt][nt][1] *= corr[mt][0];
                oacc[mt][nt][2] *= corr[mt][1]; oacc[mt][nt][3] *= corr[mt][1];
            }
        }

        // O += P @ V  (full 64-key k-dim; this warp's 32 output cols)
#pragma unroll
        for (int ks = 0; ks < 8; ks++) {
            const int k0 = ks * 8;
            uint32_t af[2][4], bf[4][2];
#pragma unroll
            for (int mt = 0; mt < 2; mt++) {
                const uint32_t* ap = Ps + (wm + mt * 16 + gid) * FQLD + k0 + tg;
                af[mt][0] = ap[0];
                af[mt][1] = ap[8 * FQLD];
                af[mt][2] = ap[4];
                af[mt][3] = ap[8 * FQLD + 4];
            }
#pragma unroll
            for (int nt = 0; nt < 4; nt++) {
                const uint32_t* bp = Vs + (k0 + tg) * FVLD + wn + nt * 8 + gid;
                bf[nt][0] = bp[0];
                bf[nt][1] = bp[4 * FVLD];
            }
#pragma unroll
            for (int mt = 0; mt < 2; mt++)
#pragma unroll
                for (int nt = 0; nt < 4; nt++)
                    mma_tf32(oacc[mt][nt], af[mt], bf[nt]);
        }
    }

    // epilogue: normalize, store
#pragma unroll
    for (int mt = 0; mt < 2; mt++) {
        const float inv0 = 1.0f / l_i[mt][0];
        const float inv1 = 1.0f / l_i[mt][1];
        const int row = q0 + wm + mt * 16 + gid;
#pragma unroll
        for (int nt = 0; nt < 4; nt++) {
            const int col = wn + nt * 8 + 2 * tg;
            float2 v0 = make_float2(oacc[mt][nt][0] * inv0, oacc[mt][nt][1] * inv0);
            float2 v1 = make_float2(oacc[mt][nt][2] * inv1, oacc[mt][nt][3] * inv1);
            *(float2*)(Op + base + (size_t)row * DD + col) = v0;
            *(float2*)(Op + base + (size_t)(row + 8) * DD + col) = v1;
        }
    }
}

// ---------------- launch -----------------------------------------------------
extern "C" void kernel_launch(void* const* d_in, const int* in_sizes, int n_in,
                              void* d_out, int out_size) {
    (void)in_sizes; (void)n_in; (void)out_size;
    const float* q  = (const float*)d_in[0];
    const float* k  = (const float*)d_in[1];
    const float* v  = (const float*)d_in[2];
    const float* Wq = (const float*)d_in[3];
    const float* bq = (const float*)d_in[4];
    const float* Wk = (const float*)d_in[5];
    const float* bk = (const float*)d_in[6];
    const float* Wv = (const float*)d_in[7];
    const float* bv = (const float*)d_in[8];
    const float* Wo = (const float*)d_in[9];
    const float* bo = (const float*)d_in[10];
    float* out = (float*)d_out;

    float *qp, *kp, *vp, *ao;
    cudaGetSymbolAddress((void**)&qp, g_qp);
    cudaGetSymbolAddress((void**)&kp, g_kp);
    cudaGetSymbolAddress((void**)&vp, g_vp);
    cudaGetSymbolAddress((void**)&ao, g_ao);

    const int gsm_bytes = GSM_FLOATS * 4;   // 71680
    const int fsm_bytes = FSM_FLOATS * 4;   // 107520
    cudaFuncSetAttribute(gemm_mma, cudaFuncAttributeMaxDynamicSharedMemorySize,
                         gsm_bytes);
    cudaFuncSetAttribute(flash_mma, cudaFuncAttributeMaxDynamicSharedMemorySize,
                         fsm_bytes);

    dim3 gemm_grid(DD / GTN, MM / GTM);   // (8, 64)
    gemm_mma<<<gemm_grid, 256, gsm_bytes>>>(q, Wq, bq, qp);
    gemm_mma<<<gemm_grid, 256, gsm_bytes>>>(k, Wk, bk, kp);
    gemm_mma<<<gemm_grid, 256, gsm_bytes>>>(v, Wv, bv, vp);

    dim3 attn_grid(SS / FBQ, HH, BB);     // (16, 16, 4)
    flash_mma<<<attn_grid, 256, fsm_bytes>>>(qp, kp, vp, ao);

    gemm_mma<<<gemm_grid, 256, gsm_bytes>>>(ao, Wo, bo, out);
}

// round 6
// speedup vs baseline: 1.1727x; 1.1727x over previous
#include <cuda_runtime.h>
#include <cuda_bf16.h>
#include <math.h>
#include <stdint.h>

// Problem constants
#define BB 4
#define SS 2048
#define DD 1024
#define HH 16
#define DKK 64
#define MM (BB * SS)   // 8192
#define GK 1024

// ---------------- scratch (device globals; no runtime alloc allowed) --------
__device__ float g_qp[(size_t)MM * DD];
__device__ float g_kp[(size_t)MM * DD];
__device__ float g_vp[(size_t)MM * DD];
__device__ float g_ao[(size_t)MM * DD];

// ==================== helpers ================================================
__device__ __forceinline__ uint32_t f2tf32(float x) {
    uint32_t u;
    asm("cvt.rna.tf32.f32 %0, %1;" : "=r"(u) : "f"(x));
    return u;
}

__device__ __forceinline__ uint32_t smem_u32(const void* p) {
    uint32_t a;
    asm("{ .reg .u64 t; cvta.to.shared.u64 t, %1; cvt.u32.u64 %0, t; }"
        : "=r"(a) : "l"(p));
    return a;
}

__device__ __forceinline__ void cp_async16(uint32_t dst, const void* src) {
    asm volatile("cp.async.ca.shared.global [%0], [%1], 16;"
                 :: "r"(dst), "l"(src));
}
#define CP_COMMIT() asm volatile("cp.async.commit_group;" ::: "memory")
#define CP_WAIT(N)  asm volatile("cp.async.wait_group %0;" :: "n"(N) : "memory")

// m16n8k8 tf32 mma (legacy tensor core; valid on compute_103 virtual arch)
__device__ __forceinline__ void mma_tf32(float* c, const uint32_t* a,
                                         const uint32_t* b) {
    asm volatile(
        "mma.sync.aligned.m16n8k8.row.col.f32.tf32.tf32.f32 "
        "{%0,%1,%2,%3}, {%4,%5,%6,%7}, {%8,%9}, {%0,%1,%2,%3};"
        : "+f"(c[0]), "+f"(c[1]), "+f"(c[2]), "+f"(c[3])
        : "r"(a[0]), "r"(a[1]), "r"(a[2]), "r"(a[3]), "r"(b[0]), "r"(b[1]));
}

// ==================== GEMM: C[M,N] = A[M,K] @ W[K,N] + bias ================
// Epilogue modes: oscale multiplies (acc+bias); oround rounds result to tf32
// so downstream flash can consume raw bytes via cp.async.
#define GTM 128
#define GTN 128
#define GKC 32
#define ALD 36
#define BLD 136
#define ABUF (GTM * ALD)
#define BBUF (GKC * BLD)
#define GSM_FLOATS (2 * (ABUF + BBUF))   // 71680 B

__global__ void __launch_bounds__(256)
gemm_mma(const float* __restrict__ A, const float* __restrict__ W,
         const float* __restrict__ bias, float* __restrict__ C,
         float oscale, int oround) {
    extern __shared__ __align__(16) uint32_t gsm[];

    const int tid = threadIdx.x;
    const int wid = tid >> 5, lane = tid & 31;
    const int gid = lane >> 2, tg = lane & 3;
    const int bm = blockIdx.y * GTM, bn = blockIdx.x * GTN;
    const int wm = (wid >> 1) * 32, wn = (wid & 1) * 64;

    float acc[2][8][4];
#pragma unroll
    for (int mt = 0; mt < 2; mt++)
#pragma unroll
        for (int nt = 0; nt < 8; nt++)
#pragma unroll
            for (int c = 0; c < 4; c++) acc[mt][nt][c] = 0.0f;

    const int arow = tid >> 3, acol = (tid & 7) * 4;
    const int brow = tid >> 5, bcol = (tid & 31) * 4;

    float4 ar[4], br[4];

    auto loadAB = [&](int kc) {
        const float* ap = A + (size_t)(bm + arow) * GK + kc * GKC + acol;
#pragma unroll
        for (int i = 0; i < 4; i++)
            ar[i] = *(const float4*)(ap + (size_t)(32 * i) * GK);
        const float* bp = W + (size_t)(kc * GKC + brow) * DD + bn + bcol;
#pragma unroll
        for (int i = 0; i < 4; i++)
            br[i] = *(const float4*)(bp + (size_t)(8 * i) * DD);
    };

    auto storeAB = [&](int buf) {
        uint32_t* As = gsm + buf * ABUF;
        uint32_t* Bs = gsm + 2 * ABUF + buf * BBUF;
#pragma unroll
        for (int i = 0; i < 4; i++) {
            uint32_t* p = As + (arow + 32 * i) * ALD + acol;
            p[0] = f2tf32(ar[i].x); p[1] = f2tf32(ar[i].y);
            p[2] = f2tf32(ar[i].z); p[3] = f2tf32(ar[i].w);
        }
#pragma unroll
        for (int i = 0; i < 4; i++) {
            uint32_t* p = Bs + (brow + 8 * i) * BLD + bcol;
            p[0] = f2tf32(br[i].x); p[1] = f2tf32(br[i].y);
            p[2] = f2tf32(br[i].z); p[3] = f2tf32(br[i].w);
        }
    };

    auto compute = [&](int buf) {
        const uint32_t* As = gsm + buf * ABUF;
        const uint32_t* Bs = gsm + 2 * ABUF + buf * BBUF;
#pragma unroll
        for (int ks = 0; ks < 4; ks++) {
            const int k0 = ks * 8;
            uint32_t af[2][4], bf[8][2];
#pragma unroll
            for (int mt = 0; mt < 2; mt++) {
                const uint32_t* p = As + (wm + mt * 16 + gid) * ALD + k0 + tg;
                af[mt][0] = p[0];
                af[mt][1] = p[8 * ALD];
                af[mt][2] = p[4];
                af[mt][3] = p[8 * ALD + 4];
            }
#pragma unroll
            for (int nt = 0; nt < 8; nt++) {
                const uint32_t* p = Bs + (k0 + tg) * BLD + wn + nt * 8 + gid;
                bf[nt][0] = p[0];
                bf[nt][1] = p[4 * BLD];
            }
#pragma unroll
            for (int mt = 0; mt < 2; mt++)
#pragma unroll
                for (int nt = 0; nt < 8; nt++)
                    mma_tf32(acc[mt][nt], af[mt], bf[nt]);
        }
    };

    loadAB(0);
    storeAB(0);
    __syncthreads();
    for (int kc = 0; kc < GK / GKC; kc++) {
        const int buf = kc & 1;
        if (kc < GK / GKC - 1) loadAB(kc + 1);
        compute(buf);
        if (kc < GK / GKC - 1) storeAB(buf ^ 1);
        __syncthreads();
    }

    auto finish = [&](float x) -> float {
        float v = x * oscale;
        if (oround) v = __uint_as_float(f2tf32(v));
        return v;
    };

#pragma unroll
    for (int mt = 0; mt < 2; mt++) {
        const int row = bm + wm + mt * 16 + gid;
#pragma unroll
        for (int nt = 0; nt < 8; nt++) {
            const int col = bn + wn + nt * 8 + 2 * tg;
            const float b0 = __ldg(bias + col), b1 = __ldg(bias + col + 1);
            float2 v0 = make_float2(finish(acc[mt][nt][0] + b0),
                                    finish(acc[mt][nt][1] + b1));
            float2 v1 = make_float2(finish(acc[mt][nt][2] + b0),
                                    finish(acc[mt][nt][3] + b1));
            *(float2*)(C + (size_t)row * DD + col) = v0;
            *(float2*)(C + (size_t)(row + 8) * DD + col) = v1;
        }
    }
}

// ==================== Flash attention on mma.sync tf32 ======================
// Round-4 tiling (best measured): 4 warps, warp tile 32(q) x 64(k), BK=64.
// Inputs pre-rounded to tf32 (Q pre-scaled by 0.125*log2e) -> cp.async fills.
// Split commit groups hide V latency under S-compute; exp2 softmax.
#define FBQ 128
#define FQLD 68   // Q/K/P smem stride
#define FVLD 72   // V smem stride
#define KS_OFF (FBQ * FQLD)
#define VS_OFF (KS_OFF + 64 * FQLD)
#define PS_OFF (VS_OFF + 64 * FVLD)
#define FSM_FLOATS (PS_OFF + FBQ * FQLD)   // 26368 floats = 105472 B

__global__ void __launch_bounds__(128)
flash_mma(const float* __restrict__ Qp, const float* __restrict__ Kp,
          const float* __restrict__ Vp, float* __restrict__ Op) {
    extern __shared__ __align__(16) uint32_t fsm[];
    uint32_t* Qs = fsm;                  // [128][68]
    uint32_t* Ks = fsm + KS_OFF;         // [64][68]
    uint32_t* Vs = fsm + VS_OFF;         // [64][72]
    uint32_t* Ps = fsm + PS_OFF;         // [128][68]
    const uint32_t sb = smem_u32(fsm);

    const int tid = threadIdx.x;
    const int wid = tid >> 5, lane = tid & 31;
    const int gid = lane >> 2, tg = lane & 3;
    const int q0 = blockIdx.x * FBQ;
    const int h = blockIdx.y, b = blockIdx.z;
    const size_t base = (size_t)b * SS * DD + (size_t)h * DKK;
    const int wm = wid * 32;

    // Q tile via cp.async (already tf32-rounded and scaled upstream)
#pragma unroll
    for (int t = 0; t < 16; t++) {
        const int i = tid + t * 128;
        const int r = i >> 4, c = (i & 15) * 4;
        cp_async16(sb + (uint32_t)(r * FQLD + c) * 4u,
                   Qp + base + (size_t)(q0 + r) * DD + c);
    }
    CP_COMMIT();

    float m_i[2][2], l_i[2][2];
    float oacc[2][8][4];
#pragma unroll
    for (int mt = 0; mt < 2; mt++) {
        m_i[mt][0] = -1e30f; m_i[mt][1] = -1e30f;
        l_i[mt][0] = 0.0f;   l_i[mt][1] = 0.0f;
#pragma unroll
        for (int nt = 0; nt < 8; nt++)
#pragma unroll
            for (int c = 0; c < 4; c++) oacc[mt][nt][c] = 0.0f;
    }

    for (int kb = 0; kb < SS / 64; kb++) {
        __syncthreads();   // prev iter's reads of Ks/Vs complete
        // issue K then V loads as separate commit groups
#pragma unroll
        for (int t = 0; t < 8; t++) {
            const int i = tid + t * 128;
            const int r = i >> 4, c = (i & 15) * 4;
            cp_async16(sb + (uint32_t)(KS_OFF + r * FQLD + c) * 4u,
                       Kp + base + (size_t)(kb * 64 + r) * DD + c);
        }
        CP_COMMIT();
#pragma unroll
        for (int t = 0; t < 8; t++) {
            const int i = tid + t * 128;
            const int r = i >> 4, c = (i & 15) * 4;
            cp_async16(sb + (uint32_t)(VS_OFF + r * FVLD + c) * 4u,
                       Vp + base + (size_t)(kb * 64 + r) * DD + c);
        }
        CP_COMMIT();
        CP_WAIT(1);        // K (and Q on iter 0) landed; V may be in flight
        __syncthreads();

        // S = Q @ K^T
        float s[2][8][4];
#pragma unroll
        for (int mt = 0; mt < 2; mt++)
#pragma unroll
            for (int nt = 0; nt < 8; nt++)
#pragma unroll
                for (int c = 0; c < 4; c++) s[mt][nt][c] = 0.0f;

#pragma unroll
        for (int ks = 0; ks < 8; ks++) {
            const int k0 = ks * 8;
            uint32_t af[2][4], bf[8][2];
#pragma unroll
            for (int mt = 0; mt < 2; mt++) {
                const uint32_t* ap = Qs + (wm + mt * 16 + gid) * FQLD + k0 + tg;
                af[mt][0] = ap[0];
                af[mt][1] = ap[8 * FQLD];
                af[mt][2] = ap[4];
                af[mt][3] = ap[8 * FQLD + 4];
            }
#pragma unroll
            for (int nt = 0; nt < 8; nt++) {
                const uint32_t* bp = Ks + (nt * 8 + gid) * FQLD + k0 + tg;
                bf[nt][0] = bp[0];
                bf[nt][1] = bp[4];
            }
#pragma unroll
            for (int mt = 0; mt < 2; mt++)
#pragma unroll
                for (int nt = 0; nt < 8; nt++)
                    mma_tf32(s[mt][nt], af[mt], bf[nt]);
        }

        // per-warp online softmax in base-2 (scale folded into Q upstream)
#pragma unroll
        for (int mt = 0; mt < 2; mt++) {
            float mx0 = -1e30f, mx1 = -1e30f;
#pragma unroll
            for (int nt = 0; nt < 8; nt++) {
                mx0 = fmaxf(mx0, fmaxf(s[mt][nt][0], s[mt][nt][1]));
                mx1 = fmaxf(mx1, fmaxf(s[mt][nt][2], s[mt][nt][3]));
            }
#pragma unroll
            for (int m = 1; m <= 2; m <<= 1) {
                mx0 = fmaxf(mx0, __shfl_xor_sync(0xffffffffu, mx0, m));
                mx1 = fmaxf(mx1, __shfl_xor_sync(0xffffffffu, mx1, m));
            }
            const float mn0 = fmaxf(m_i[mt][0], mx0);
            const float mn1 = fmaxf(m_i[mt][1], mx1);
            const float corr0 = exp2f(m_i[mt][0] - mn0);
            const float corr1 = exp2f(m_i[mt][1] - mn1);
            float sum0 = 0.0f, sum1 = 0.0f;
#pragma unroll
            for (int nt = 0; nt < 8; nt++) {
                s[mt][nt][0] = exp2f(s[mt][nt][0] - mn0);
                s[mt][nt][1] = exp2f(s[mt][nt][1] - mn0);
                s[mt][nt][2] = exp2f(s[mt][nt][2] - mn1);
                s[mt][nt][3] = exp2f(s[mt][nt][3] - mn1);
                sum0 += s[mt][nt][0] + s[mt][nt][1];
                sum1 += s[mt][nt][2] + s[mt][nt][3];
            }
#pragma unroll
            for (int m = 1; m <= 2; m <<= 1) {
                sum0 += __shfl_xor_sync(0xffffffffu, sum0, m);
                sum1 += __shfl_xor_sync(0xffffffffu, sum1, m);
            }
            l_i[mt][0] = l_i[mt][0] * corr0 + sum0;
            l_i[mt][1] = l_i[mt][1] * corr1 + sum1;
            m_i[mt][0] = mn0;
            m_i[mt][1] = mn1;
#pragma unroll
            for (int nt = 0; nt < 8; nt++) {
                oacc[mt][nt][0] *= corr0; oacc[mt][nt][1] *= corr0;
                oacc[mt][nt][2] *= corr1; oacc[mt][nt][3] *= corr1;
            }

            // write P fragments (C layout) to warp-private smem rows
#pragma unroll
            for (int nt = 0; nt < 8; nt++) {
                uint32_t* pp = Ps + (wm + mt * 16 + gid) * FQLD + nt * 8 + 2 * tg;
                uint2 lo = make_uint2(f2tf32(s[mt][nt][0]), f2tf32(s[mt][nt][1]));
                uint2 hi = make_uint2(f2tf32(s[mt][nt][2]), f2tf32(s[mt][nt][3]));
                *(uint2*)pp = lo;
                *(uint2*)(pp + 8 * FQLD) = hi;
            }
        }
        __syncwarp();
        CP_WAIT(0);        // V landed
        __syncthreads();   // V visible to all warps

        // O += P @ V
#pragma unroll
        for (int ks = 0; ks < 8; ks++) {
            const int k0 = ks * 8;
            uint32_t af[2][4], bf[8][2];
#pragma unroll
            for (int mt = 0; mt < 2; mt++) {
                const uint32_t* ap = Ps + (wm + mt * 16 + gid) * FQLD + k0 + tg;
                af[mt][0] = ap[0];
                af[mt][1] = ap[8 * FQLD];
                af[mt][2] = ap[4];
                af[mt][3] = ap[8 * FQLD + 4];
            }
#pragma unroll
            for (int nt = 0; nt < 8; nt++) {
                const uint32_t* bp = Vs + (k0 + tg) * FVLD + nt * 8 + gid;
                bf[nt][0] = bp[0];
                bf[nt][1] = bp[4 * FVLD];
            }
#pragma unroll
            for (int mt = 0; mt < 2; mt++)
#pragma unroll
                for (int nt = 0; nt < 8; nt++)
                    mma_tf32(oacc[mt][nt], af[mt], bf[nt]);
        }
    }

    // epilogue: normalize, store
#pragma unroll
    for (int mt = 0; mt < 2; mt++) {
        const float inv0 = 1.0f / l_i[mt][0];
        const float inv1 = 1.0f / l_i[mt][1];
        const int row = q0 + wm + mt * 16 + gid;
#pragma unroll
        for (int nt = 0; nt < 8; nt++) {
            const int col = nt * 8 + 2 * tg;
            float2 v0 = make_float2(oacc[mt][nt][0] * inv0, oacc[mt][nt][1] * inv0);
            float2 v1 = make_float2(oacc[mt][nt][2] * inv1, oacc[mt][nt][3] * inv1);
            *(float2*)(Op + base + (size_t)row * DD + col) = v0;
            *(float2*)(Op + base + (size_t)(row + 8) * DD + col) = v1;
        }
    }
}

// ---------------- launch -----------------------------------------------------
extern "C" void kernel_launch(void* const* d_in, const int* in_sizes, int n_in,
                              void* d_out, int out_size) {
    (void)in_sizes; (void)n_in; (void)out_size;
    const float* q  = (const float*)d_in[0];
    const float* k  = (const float*)d_in[1];
    const float* v  = (const float*)d_in[2];
    const float* Wq = (const float*)d_in[3];
    const float* bq = (const float*)d_in[4];
    const float* Wk = (const float*)d_in[5];
    const float* bk = (const float*)d_in[6];
    const float* Wv = (const float*)d_in[7];
    const float* bv = (const float*)d_in[8];
    const float* Wo = (const float*)d_in[9];
    const float* bo = (const float*)d_in[10];
    float* out = (float*)d_out;

    float *qp, *kp, *vp, *ao;
    cudaGetSymbolAddress((void**)&qp, g_qp);
    cudaGetSymbolAddress((void**)&kp, g_kp);
    cudaGetSymbolAddress((void**)&vp, g_vp);
    cudaGetSymbolAddress((void**)&ao, g_ao);

    const int gsm_bytes = GSM_FLOATS * 4;   // 71680
    const int fsm_bytes = FSM_FLOATS * 4;   // 105472
    cudaFuncSetAttribute(gemm_mma, cudaFuncAttributeMaxDynamicSharedMemorySize,
                         gsm_bytes);
    cudaFuncSetAttribute(flash_mma, cudaFuncAttributeMaxDynamicSharedMemorySize,
                         fsm_bytes);

    const float qscale = 0.125f * 1.44269504088896340736f;  // 1/sqrt(dk)*log2(e)

    dim3 gemm_grid(DD / GTN, MM / GTM);   // (8, 64)
    gemm_mma<<<gemm_grid, 256, gsm_bytes>>>(q, Wq, bq, qp, qscale, 1);
    gemm_mma<<<gemm_grid, 256, gsm_bytes>>>(k, Wk, bk, kp, 1.0f, 1);
    gemm_mma<<<gemm_grid, 256, gsm_bytes>>>(v, Wv, bv, vp, 1.0f, 1);

    dim3 attn_grid(SS / FBQ, HH, BB);     // (16, 16, 4)
    flash_mma<<<attn_grid, 128, fsm_bytes>>>(qp, kp, vp, ao);

    gemm_mma<<<gemm_grid, 256, gsm_bytes>>>(ao, Wo, bo, out, 1.0f, 0);
}